// round 5
// baseline (speedup 1.0000x reference)
#include <cuda_runtime.h>
#include <math.h>

#define BATCH 256
#define SEQ   512
#define DIN   64
#define HID   256

__device__ float g_bufA[(size_t)BATCH * SEQ * HID];   // 128 MiB
__device__ float g_bufB[(size_t)BATCH * SEQ * HID];   // 128 MiB
__device__ float g_hfin[(size_t)BATCH * HID];

// ---------------------------------------------------------------------------
// helpers
// ---------------------------------------------------------------------------
__device__ __forceinline__ unsigned long long ffma2(unsigned long long a,
                                                    unsigned long long b,
                                                    unsigned long long c) {
    unsigned long long d;
    asm("fma.rn.f32x2 %0, %1, %2, %3;" : "=l"(d) : "l"(a), "l"(b), "l"(c));
    return d;
}
__device__ __forceinline__ float2 u2f(unsigned long long v) {
    float2 r;
    asm("mov.b64 {%0, %1}, %2;" : "=f"(r.x), "=f"(r.y) : "l"(v));
    return r;
}
__device__ __forceinline__ unsigned long long pack2(float a, float b) {
    unsigned long long r;
    asm("mov.b64 %0, {%1, %2};" : "=l"(r) : "f"(a), "f"(b));
    return r;
}
__device__ __forceinline__ float tanh_fast(float x) {
    float r;
    asm("tanh.approx.f32 %0, %1;" : "=f"(r) : "f"(x));
    return r;
}

// ---------------------------------------------------------------------------
// Recurrence v4: 128 blocks x 512 threads, 2 batch rows per block.
// Thread t: op = t>>2 -> outputs o0=2op, o0+1;  kq = t&3 -> k strip of 64.
// Per output: 44 weight floats in regs (22 u64), 20 in smem (5 u64).
// Halved h-LDS vs v1: each h value feeds 2 outputs.
// h chunks at 68-float skew -> the 4 kq read addresses are bank-disjoint.
// Reduction across 4 kq lanes via 2 shfl.xor rounds; every thread is the
// unique writer of one (output, row) h element.
// ---------------------------------------------------------------------------
#define W4_SMEM_BYTES (10 * 512 * 16)         // 80 KB: ulonglong2[10][512]
#define H4_ROW_F      272                     // 4 chunks * 68 floats
#define H4_BUF_F      (2 * H4_ROW_F)          // 544 floats (2 rows)
#define RNN4_SMEM     (W4_SMEM_BYTES + 2 * H4_BUF_F * 4)

__global__ __launch_bounds__(512, 1) void rnn_recur4(
    const float* __restrict__ xp,      // [BATCH, SEQ, HID] (bias pre-added)
    const float* __restrict__ Whh,     // [HID, HID]
    float* __restrict__ out_seq,       // [BATCH, SEQ, HID] or null
    float* __restrict__ out_final)     // [BATCH, HID] or null
{
    extern __shared__ char smem_raw[];
    ulonglong2* wsm  = reinterpret_cast<ulonglong2*>(smem_raw);  // [10][512]
    float*      hbuf = reinterpret_cast<float*>(smem_raw + W4_SMEM_BYTES);

    const int t  = threadIdx.x;
    const int op = t >> 2;          // 0..127
    const int kq = t & 3;           // 0..3
    const int o0 = op * 2;
    const int k0 = kq * 64;

    // ---- weights: per output, pairs 0..21 in regs, pairs 22..31 in smem ----
    unsigned long long w0[22], w1[22];
    {
        const ulonglong2* wr0 =
            reinterpret_cast<const ulonglong2*>(Whh + o0 * HID + k0);
        const ulonglong2* wr1 =
            reinterpret_cast<const ulonglong2*>(Whh + (o0 + 1) * HID + k0);
#pragma unroll
        for (int j = 0; j < 11; j++) {
            ulonglong2 v0 = wr0[j];
            ulonglong2 v1 = wr1[j];
            w0[2 * j] = v0.x;  w0[2 * j + 1] = v0.y;
            w1[2 * j] = v1.x;  w1[2 * j + 1] = v1.y;
        }
#pragma unroll
        for (int j = 0; j < 5; j++) {
            wsm[j * 512 + t]       = wr0[11 + j];
            wsm[(5 + j) * 512 + t] = wr1[11 + j];
        }
    }

    for (int i = t; i < 2 * H4_BUF_F; i += 512) hbuf[i] = 0.0f;
    __syncthreads();

    // this thread's unique (output, row) write slot
    const int o_w   = o0 + (kq >> 1);
    const int row_w = kq & 1;
    const int grow  = blockIdx.x * 2 + row_w;
    const float* myxp = xp + ((size_t)grow * SEQ) * HID + o_w;
    float* myout = out_seq ? out_seq + ((size_t)grow * SEQ) * HID + o_w
                           : (float*)0;
    const int wslot = row_w * H4_ROW_F + (o_w >> 6) * 68 + (o_w & 63);

    int   buf   = 0;
    float hlast = 0.0f;

    for (int s = 0; s < SEQ; s++) {
        float xv = __ldg(myxp + (size_t)s * HID);

        const float* hb = hbuf + buf * H4_BUF_F;
        const ulonglong2* h0 =
            reinterpret_cast<const ulonglong2*>(hb + kq * 68);
        const ulonglong2* h1 =
            reinterpret_cast<const ulonglong2*>(hb + H4_ROW_F + kq * 68);

        unsigned long long a00 = 0ull, a01 = 0ull, a10 = 0ull, a11 = 0ull;
#pragma unroll
        for (int jj = 0; jj < 11; jj++) {       // register weights
            ulonglong2 hv0 = h0[jj];
            ulonglong2 hv1 = h1[jj];
            a00 = ffma2(w0[2 * jj],     hv0.x, a00);
            a00 = ffma2(w0[2 * jj + 1], hv0.y, a00);
            a01 = ffma2(w0[2 * jj],     hv1.x, a01);
            a01 = ffma2(w0[2 * jj + 1], hv1.y, a01);
            a10 = ffma2(w1[2 * jj],     hv0.x, a10);
            a10 = ffma2(w1[2 * jj + 1], hv0.y, a10);
            a11 = ffma2(w1[2 * jj],     hv1.x, a11);
            a11 = ffma2(w1[2 * jj + 1], hv1.y, a11);
        }
#pragma unroll
        for (int jj = 11; jj < 16; jj++) {      // smem weights
            ulonglong2 hv0 = h0[jj];
            ulonglong2 hv1 = h1[jj];
            ulonglong2 wv0 = wsm[(jj - 11) * 512 + t];
            ulonglong2 wv1 = wsm[(jj - 6) * 512 + t];
            a00 = ffma2(wv0.x, hv0.x, a00);
            a00 = ffma2(wv0.y, hv0.y, a00);
            a01 = ffma2(wv0.x, hv1.x, a01);
            a01 = ffma2(wv0.y, hv1.y, a01);
            a10 = ffma2(wv1.x, hv0.x, a10);
            a10 = ffma2(wv1.y, hv0.y, a10);
            a11 = ffma2(wv1.x, hv1.x, a11);
            a11 = ffma2(wv1.y, hv1.y, a11);
        }

        float2 f;
        f = u2f(a00); float d00 = f.x + f.y;
        f = u2f(a01); float d01 = f.x + f.y;
        f = u2f(a10); float d10 = f.x + f.y;
        f = u2f(a11); float d11 = f.x + f.y;
        d00 += __shfl_xor_sync(0xffffffffu, d00, 1);
        d01 += __shfl_xor_sync(0xffffffffu, d01, 1);
        d10 += __shfl_xor_sync(0xffffffffu, d10, 1);
        d11 += __shfl_xor_sync(0xffffffffu, d11, 1);
        d00 += __shfl_xor_sync(0xffffffffu, d00, 2);
        d01 += __shfl_xor_sync(0xffffffffu, d01, 2);
        d10 += __shfl_xor_sync(0xffffffffu, d10, 2);
        d11 += __shfl_xor_sync(0xffffffffu, d11, 2);

        // kq -> (output, row): 0:(o0,r0) 1:(o0,r1) 2:(o0+1,r0) 3:(o0+1,r1)
        float d  = (kq == 0) ? d00 : (kq == 1) ? d01 : (kq == 2) ? d10 : d11;
        float hn = tanh_fast(d + xv);
        hlast = hn;
        hbuf[(buf ^ 1) * H4_BUF_F + wslot] = hn;
        if (myout) myout[(size_t)s * HID] = hn;

        __syncthreads();
        buf ^= 1;
    }

    if (out_final) out_final[(size_t)grow * HID + o_w] = hlast;
}

// ---------------------------------------------------------------------------
// GEMM v3 (unchanged, proven): Y[M,256] = X[M,K] @ W[256,K]^T + (ba+bb)
// Block tile 128x128, 256 threads, 8x8 thread tile, double-buffered smem.
// ---------------------------------------------------------------------------
template <int K>
__global__ __launch_bounds__(256, 2) void gemm3(
    const float* __restrict__ X, const float* __restrict__ W,
    const float* __restrict__ ba, const float* __restrict__ bb,
    float* __restrict__ Y)
{
    __shared__ float xs[2][16][128];
    __shared__ float ws[2][16][128];
    const int t  = threadIdx.x;
    const int tx = t & 15;
    const int ty = t >> 4;
    const size_t m0 = (size_t)blockIdx.x * 128;
    const int    n0 = blockIdx.y * 128;

    unsigned long long acc[8][4];
#pragma unroll
    for (int mi = 0; mi < 8; mi++)
#pragma unroll
        for (int ni = 0; ni < 4; ni++) acc[mi][ni] = 0ull;

    const int r = t & 127;
    const float* src_base = (t < 128) ? (X + (m0 + r) * K)
                                      : (W + (size_t)(n0 + r) * K);

    float4 pf[4];
#pragma unroll
    for (int q = 0; q < 4; q++)
        pf[q] = reinterpret_cast<const float4*>(src_base)[q];

    int sb = 0;
    {
        float* dst = (t < 128) ? &xs[0][0][r] : &ws[0][0][r];
#pragma unroll
        for (int q = 0; q < 4; q++) {
            dst[(4 * q + 0) * 128] = pf[q].x;
            dst[(4 * q + 1) * 128] = pf[q].y;
            dst[(4 * q + 2) * 128] = pf[q].z;
            dst[(4 * q + 3) * 128] = pf[q].w;
        }
    }
    __syncthreads();

    for (int kc = 0; kc < K; kc += 16) {
        const bool have_next = (kc + 16 < K);
        if (have_next) {
            const float4* src =
                reinterpret_cast<const float4*>(src_base + kc + 16);
#pragma unroll
            for (int q = 0; q < 4; q++) pf[q] = src[q];
        }

#pragma unroll
        for (int k = 0; k < 16; k++) {
            float4 a0 = *reinterpret_cast<const float4*>(&xs[sb][k][ty * 8]);
            float4 a1 = *reinterpret_cast<const float4*>(&xs[sb][k][ty * 8 + 4]);
            ulonglong2 b0 =
                *reinterpret_cast<const ulonglong2*>(&ws[sb][k][tx * 8]);
            ulonglong2 b1 =
                *reinterpret_cast<const ulonglong2*>(&ws[sb][k][tx * 8 + 4]);
            float am[8] = {a0.x, a0.y, a0.z, a0.w, a1.x, a1.y, a1.z, a1.w};
            unsigned long long bp0 = b0.x, bp1 = b0.y, bp2 = b1.x, bp3 = b1.y;
#pragma unroll
            for (int mi = 0; mi < 8; mi++) {
                unsigned long long am2 = pack2(am[mi], am[mi]);
                acc[mi][0] = ffma2(bp0, am2, acc[mi][0]);
                acc[mi][1] = ffma2(bp1, am2, acc[mi][1]);
                acc[mi][2] = ffma2(bp2, am2, acc[mi][2]);
                acc[mi][3] = ffma2(bp3, am2, acc[mi][3]);
            }
        }

        if (have_next) {
            float* dst = (t < 128) ? &xs[sb ^ 1][0][r] : &ws[sb ^ 1][0][r];
#pragma unroll
            for (int q = 0; q < 4; q++) {
                dst[(4 * q + 0) * 128] = pf[q].x;
                dst[(4 * q + 1) * 128] = pf[q].y;
                dst[(4 * q + 2) * 128] = pf[q].z;
                dst[(4 * q + 3) * 128] = pf[q].w;
            }
            __syncthreads();
            sb ^= 1;
        }
    }

    float bias[8];
#pragma unroll
    for (int i = 0; i < 8; i++)
        bias[i] = ba[n0 + tx * 8 + i] + bb[n0 + tx * 8 + i];

#pragma unroll
    for (int mi = 0; mi < 8; mi++) {
        float* yrow = Y + (m0 + ty * 8 + mi) * HID + n0 + tx * 8;
        float2 f0 = u2f(acc[mi][0]);
        float2 f1 = u2f(acc[mi][1]);
        float2 f2 = u2f(acc[mi][2]);
        float2 f3 = u2f(acc[mi][3]);
        float4 oA = make_float4(f0.x + bias[0], f0.y + bias[1],
                                f1.x + bias[2], f1.y + bias[3]);
        float4 oB = make_float4(f2.x + bias[4], f2.y + bias[5],
                                f3.x + bias[6], f3.y + bias[7]);
        reinterpret_cast<float4*>(yrow)[0] = oA;
        reinterpret_cast<float4*>(yrow)[1] = oB;
    }
}

// ---------------------------------------------------------------------------
// out[b] = sigmoid(h2[b,:] . Wfc + bfc)
// ---------------------------------------------------------------------------
__global__ void fc_sigmoid_kernel(const float* __restrict__ h2,
                                  const float* __restrict__ Wfc,
                                  const float* __restrict__ bfc,
                                  float* __restrict__ out)
{
    __shared__ float wf[HID];
    const int t = threadIdx.x;
    wf[t] = Wfc[t];
    __syncthreads();
    const float* hb = h2 + (size_t)t * HID;
    float s = 0.0f;
#pragma unroll 8
    for (int k = 0; k < HID; k++) s = fmaf(hb[k], wf[k], s);
    float z = s + bfc[0];
    out[t] = 1.0f / (1.0f + expf(-z));
}

// ---------------------------------------------------------------------------
// launch
// ---------------------------------------------------------------------------
extern "C" void kernel_launch(void* const* d_in, const int* in_sizes, int n_in,
                              void* d_out, int out_size)
{
    const float* x     = (const float*)d_in[0];
    const float* W_ih0 = (const float*)d_in[1];
    const float* W_hh0 = (const float*)d_in[2];
    const float* b_ih0 = (const float*)d_in[3];
    const float* b_hh0 = (const float*)d_in[4];
    const float* W_ih1 = (const float*)d_in[5];
    const float* W_hh1 = (const float*)d_in[6];
    const float* b_ih1 = (const float*)d_in[7];
    const float* b_hh1 = (const float*)d_in[8];
    const float* W_fc  = (const float*)d_in[9];
    const float* b_fc  = (const float*)d_in[10];
    float* out = (float*)d_out;

    float *bufA, *bufB, *hfin;
    cudaGetSymbolAddress((void**)&bufA, g_bufA);
    cudaGetSymbolAddress((void**)&bufB, g_bufB);
    cudaGetSymbolAddress((void**)&hfin, g_hfin);

    cudaFuncSetAttribute(rnn_recur4,
                         cudaFuncAttributeMaxDynamicSharedMemorySize,
                         RNN4_SMEM);

    const dim3 ggrid((BATCH * SEQ) / 128, 2);

    // A: xp0 = x @ W_ih0^T + (b_ih0 + b_hh0)
    gemm3<DIN><<<ggrid, 256>>>(x, W_ih0, b_ih0, b_hh0, bufA);
    // B: layer-0 recurrence -> h1 sequence
    rnn_recur4<<<BATCH / 2, 512, RNN4_SMEM>>>(bufA, W_hh0, bufB, (float*)0);
    // C: xp1 = h1 @ W_ih1^T + (b_ih1 + b_hh1)
    gemm3<HID><<<ggrid, 256>>>(bufB, W_ih1, b_ih1, b_hh1, bufA);
    // D: layer-1 recurrence -> final hidden only
    rnn_recur4<<<BATCH / 2, 512, RNN4_SMEM>>>(bufA, W_hh1, (float*)0, hfin);
    // E: fc + sigmoid
    fc_sigmoid_kernel<<<1, HID>>>(hfin, W_fc, b_fc, out);
}

// round 6
// speedup vs baseline: 1.0195x; 1.0195x over previous
#include <cuda_runtime.h>
#include <math.h>

#define BATCH 256
#define SEQ   512
#define DIN   64
#define HID   256

__device__ float g_bufA[(size_t)BATCH * SEQ * HID];   // 128 MiB
__device__ float g_bufB[(size_t)BATCH * SEQ * HID];   // 128 MiB
__device__ float g_hfin[(size_t)BATCH * HID];

// ---------------------------------------------------------------------------
// helpers
// ---------------------------------------------------------------------------
__device__ __forceinline__ unsigned long long ffma2(unsigned long long a,
                                                    unsigned long long b,
                                                    unsigned long long c) {
    unsigned long long d;
    asm("fma.rn.f32x2 %0, %1, %2, %3;" : "=l"(d) : "l"(a), "l"(b), "l"(c));
    return d;
}
__device__ __forceinline__ float2 u2f(unsigned long long v) {
    float2 r;
    asm("mov.b64 {%0, %1}, %2;" : "=f"(r.x), "=f"(r.y) : "l"(v));
    return r;
}
__device__ __forceinline__ unsigned long long pack2(float a, float b) {
    unsigned long long r;
    asm("mov.b64 %0, {%1, %2};" : "=l"(r) : "f"(a), "f"(b));
    return r;
}
__device__ __forceinline__ float tanh_fast(float x) {
    float r;
    asm("tanh.approx.f32 %0, %1;" : "=f"(r) : "f"(x));
    return r;
}
// pack two f32 into one bf16x2 register: lo=cvt(a), hi=cvt(b)
__device__ __forceinline__ unsigned int f2bf2(float a, float b) {
    unsigned int r;
    asm("cvt.rn.bf16x2.f32 %0, %2, %1;" : "=r"(r) : "f"(a), "f"(b));
    return r;
}
// expand bf16x2 reg -> f32x2 u64 (2 ALU ops + reg-pair mov)
__device__ __forceinline__ unsigned long long bf2f2(unsigned int b) {
    unsigned long long r;
    asm("{\n\t"
        ".reg .b32 lo, hi;\n\t"
        "shl.b32 lo, %1, 16;\n\t"
        "and.b32 hi, %1, 0xffff0000;\n\t"
        "mov.b64 %0, {lo, hi};\n\t"
        "}"
        : "=l"(r) : "r"(b));
    return r;
}

// ---------------------------------------------------------------------------
// Recurrence v5: v1 structure (128 blocks x 512 threads, thread=(o, half),
// 2 batch rows per block) but ALL 128 weight floats per thread live in
// registers: 72 as f32x2 (36 u64) + 56 as bf16x2 (28 u32, expanded in-loop
// on the idle ALU pipe). Zero smem weight traffic.
// ---------------------------------------------------------------------------
#define NQ_F32 18     // ulonglong2 h-chunks covered by f32 weights (72 floats)
#define NQ_BF  14     // chunks covered by bf16 weights (56 floats)

__global__ __launch_bounds__(512, 1) void rnn_recur5(
    const float* __restrict__ xp,      // [BATCH, SEQ, HID] (bias pre-added)
    const float* __restrict__ Whh,     // [HID, HID]
    float* __restrict__ out_seq,       // [BATCH, SEQ, HID] or null
    float* __restrict__ out_final)     // [BATCH, HID] or null
{
    __shared__ __align__(16) float hbuf[2][2][272];

    const int t     = threadIdx.x;
    const int o     = t >> 1;
    const int half  = t & 1;
    const int myrow = blockIdx.x * 2 + half;

    // ---- weights: Whh[o, half*128 .. +127] ----
    const ulonglong2* wr =
        reinterpret_cast<const ulonglong2*>(Whh + o * HID + half * 128);

    unsigned long long w[2 * NQ_F32];   // f32x2 pairs for k 0..71
    unsigned int       wb[2 * NQ_BF];   // bf16x2 pairs for k 72..127
#pragma unroll
    for (int q = 0; q < NQ_F32; q++) {
        ulonglong2 v = wr[q];
        w[2 * q]     = v.x;
        w[2 * q + 1] = v.y;
    }
#pragma unroll
    for (int j = 0; j < NQ_BF; j++) {
        ulonglong2 v  = wr[NQ_F32 + j];
        float2     p0 = u2f(v.x);
        float2     p1 = u2f(v.y);
        wb[2 * j]     = f2bf2(p0.x, p0.y);
        wb[2 * j + 1] = f2bf2(p1.x, p1.y);
    }

    for (int idx = t; idx < 2 * 2 * 272; idx += 512)
        (&hbuf[0][0][0])[idx] = 0.0f;
    __syncthreads();

    const float* myxp  = xp + (size_t)myrow * SEQ * HID + o;
    float*       myout = out_seq ? out_seq + (size_t)myrow * SEQ * HID + o
                                 : (float*)0;

    int   buf   = 0;
    float hlast = 0.0f;

    for (int s = 0; s < SEQ; s++) {
        float xv = __ldg(myxp + (size_t)s * HID);

        const ulonglong2* h0 =
            reinterpret_cast<const ulonglong2*>(&hbuf[buf][0][half * 132]);
        const ulonglong2* h1 =
            reinterpret_cast<const ulonglong2*>(&hbuf[buf][1][half * 132]);

        unsigned long long a0 = 0ull, a1 = 0ull;
#pragma unroll
        for (int q = 0; q < NQ_F32; q++) {      // f32 register weights
            ulonglong2 v0 = h0[q], v1 = h1[q];
            a0 = ffma2(w[2 * q],     v0.x, a0);
            a0 = ffma2(w[2 * q + 1], v0.y, a0);
            a1 = ffma2(w[2 * q],     v1.x, a1);
            a1 = ffma2(w[2 * q + 1], v1.y, a1);
        }
#pragma unroll
        for (int j = 0; j < NQ_BF; j++) {       // bf16 register weights
            ulonglong2 v0 = h0[NQ_F32 + j], v1 = h1[NQ_F32 + j];
            unsigned long long wp0 = bf2f2(wb[2 * j]);
            unsigned long long wp1 = bf2f2(wb[2 * j + 1]);
            a0 = ffma2(wp0, v0.x, a0);
            a0 = ffma2(wp1, v0.y, a0);
            a1 = ffma2(wp0, v1.x, a1);
            a1 = ffma2(wp1, v1.y, a1);
        }

        float2 f0 = u2f(a0), f1 = u2f(a1);
        float  d0 = f0.x + f0.y;
        float  d1 = f1.x + f1.y;
        d0 += __shfl_xor_sync(0xffffffffu, d0, 1);
        d1 += __shfl_xor_sync(0xffffffffu, d1, 1);

        float hn = tanh_fast((half ? d1 : d0) + xv);
        hlast = hn;

        hbuf[buf ^ 1][half][o + 4 * (o >> 7)] = hn;
        if (out_seq) myout[(size_t)s * HID] = hn;

        __syncthreads();
        buf ^= 1;
    }

    if (out_final) out_final[(size_t)myrow * HID + o] = hlast;
}

// ---------------------------------------------------------------------------
// GEMM v3 (unchanged, proven): Y[M,256] = X[M,K] @ W[256,K]^T + (ba+bb)
// Block tile 128x128, 256 threads, 8x8 thread tile, double-buffered smem.
// ---------------------------------------------------------------------------
template <int K>
__global__ __launch_bounds__(256, 2) void gemm3(
    const float* __restrict__ X, const float* __restrict__ W,
    const float* __restrict__ ba, const float* __restrict__ bb,
    float* __restrict__ Y)
{
    __shared__ float xs[2][16][128];
    __shared__ float ws[2][16][128];
    const int t  = threadIdx.x;
    const int tx = t & 15;
    const int ty = t >> 4;
    const size_t m0 = (size_t)blockIdx.x * 128;
    const int    n0 = blockIdx.y * 128;

    unsigned long long acc[8][4];
#pragma unroll
    for (int mi = 0; mi < 8; mi++)
#pragma unroll
        for (int ni = 0; ni < 4; ni++) acc[mi][ni] = 0ull;

    const int r = t & 127;
    const float* src_base = (t < 128) ? (X + (m0 + r) * K)
                                      : (W + (size_t)(n0 + r) * K);

    float4 pf[4];
#pragma unroll
    for (int q = 0; q < 4; q++)
        pf[q] = reinterpret_cast<const float4*>(src_base)[q];

    int sb = 0;
    {
        float* dst = (t < 128) ? &xs[0][0][r] : &ws[0][0][r];
#pragma unroll
        for (int q = 0; q < 4; q++) {
            dst[(4 * q + 0) * 128] = pf[q].x;
            dst[(4 * q + 1) * 128] = pf[q].y;
            dst[(4 * q + 2) * 128] = pf[q].z;
            dst[(4 * q + 3) * 128] = pf[q].w;
        }
    }
    __syncthreads();

    for (int kc = 0; kc < K; kc += 16) {
        const bool have_next = (kc + 16 < K);
        if (have_next) {
            const float4* src =
                reinterpret_cast<const float4*>(src_base + kc + 16);
#pragma unroll
            for (int q = 0; q < 4; q++) pf[q] = src[q];
        }

#pragma unroll
        for (int k = 0; k < 16; k++) {
            float4 a0 = *reinterpret_cast<const float4*>(&xs[sb][k][ty * 8]);
            float4 a1 = *reinterpret_cast<const float4*>(&xs[sb][k][ty * 8 + 4]);
            ulonglong2 b0 =
                *reinterpret_cast<const ulonglong2*>(&ws[sb][k][tx * 8]);
            ulonglong2 b1 =
                *reinterpret_cast<const ulonglong2*>(&ws[sb][k][tx * 8 + 4]);
            float am[8] = {a0.x, a0.y, a0.z, a0.w, a1.x, a1.y, a1.z, a1.w};
            unsigned long long bp0 = b0.x, bp1 = b0.y, bp2 = b1.x, bp3 = b1.y;
#pragma unroll
            for (int mi = 0; mi < 8; mi++) {
                unsigned long long am2 = pack2(am[mi], am[mi]);
                acc[mi][0] = ffma2(bp0, am2, acc[mi][0]);
                acc[mi][1] = ffma2(bp1, am2, acc[mi][1]);
                acc[mi][2] = ffma2(bp2, am2, acc[mi][2]);
                acc[mi][3] = ffma2(bp3, am2, acc[mi][3]);
            }
        }

        if (have_next) {
            float* dst = (t < 128) ? &xs[sb ^ 1][0][r] : &ws[sb ^ 1][0][r];
#pragma unroll
            for (int q = 0; q < 4; q++) {
                dst[(4 * q + 0) * 128] = pf[q].x;
                dst[(4 * q + 1) * 128] = pf[q].y;
                dst[(4 * q + 2) * 128] = pf[q].z;
                dst[(4 * q + 3) * 128] = pf[q].w;
            }
            __syncthreads();
            sb ^= 1;
        }
    }

    float bias[8];
#pragma unroll
    for (int i = 0; i < 8; i++)
        bias[i] = ba[n0 + tx * 8 + i] + bb[n0 + tx * 8 + i];

#pragma unroll
    for (int mi = 0; mi < 8; mi++) {
        float* yrow = Y + (m0 + ty * 8 + mi) * HID + n0 + tx * 8;
        float2 f0 = u2f(acc[mi][0]);
        float2 f1 = u2f(acc[mi][1]);
        float2 f2 = u2f(acc[mi][2]);
        float2 f3 = u2f(acc[mi][3]);
        float4 oA = make_float4(f0.x + bias[0], f0.y + bias[1],
                                f1.x + bias[2], f1.y + bias[3]);
        float4 oB = make_float4(f2.x + bias[4], f2.y + bias[5],
                                f3.x + bias[6], f3.y + bias[7]);
        reinterpret_cast<float4*>(yrow)[0] = oA;
        reinterpret_cast<float4*>(yrow)[1] = oB;
    }
}

// ---------------------------------------------------------------------------
// out[b] = sigmoid(h2[b,:] . Wfc + bfc)
// ---------------------------------------------------------------------------
__global__ void fc_sigmoid_kernel(const float* __restrict__ h2,
                                  const float* __restrict__ Wfc,
                                  const float* __restrict__ bfc,
                                  float* __restrict__ out)
{
    __shared__ float wf[HID];
    const int t = threadIdx.x;
    wf[t] = Wfc[t];
    __syncthreads();
    const float* hb = h2 + (size_t)t * HID;
    float s = 0.0f;
#pragma unroll 8
    for (int k = 0; k < HID; k++) s = fmaf(hb[k], wf[k], s);
    float z = s + bfc[0];
    out[t] = 1.0f / (1.0f + expf(-z));
}

// ---------------------------------------------------------------------------
// launch
// ---------------------------------------------------------------------------
extern "C" void kernel_launch(void* const* d_in, const int* in_sizes, int n_in,
                              void* d_out, int out_size)
{
    const float* x     = (const float*)d_in[0];
    const float* W_ih0 = (const float*)d_in[1];
    const float* W_hh0 = (const float*)d_in[2];
    const float* b_ih0 = (const float*)d_in[3];
    const float* b_hh0 = (const float*)d_in[4];
    const float* W_ih1 = (const float*)d_in[5];
    const float* W_hh1 = (const float*)d_in[6];
    const float* b_ih1 = (const float*)d_in[7];
    const float* b_hh1 = (const float*)d_in[8];
    const float* W_fc  = (const float*)d_in[9];
    const float* b_fc  = (const float*)d_in[10];
    float* out = (float*)d_out;

    float *bufA, *bufB, *hfin;
    cudaGetSymbolAddress((void**)&bufA, g_bufA);
    cudaGetSymbolAddress((void**)&bufB, g_bufB);
    cudaGetSymbolAddress((void**)&hfin, g_hfin);

    const dim3 ggrid((BATCH * SEQ) / 128, 2);

    // A: xp0 = x @ W_ih0^T + (b_ih0 + b_hh0)
    gemm3<DIN><<<ggrid, 256>>>(x, W_ih0, b_ih0, b_hh0, bufA);
    // B: layer-0 recurrence -> h1 sequence
    rnn_recur5<<<BATCH / 2, 512>>>(bufA, W_hh0, bufB, (float*)0);
    // C: xp1 = h1 @ W_ih1^T + (b_ih1 + b_hh1)
    gemm3<HID><<<ggrid, 256>>>(bufB, W_ih1, b_ih1, b_hh1, bufA);
    // D: layer-1 recurrence -> final hidden only
    rnn_recur5<<<BATCH / 2, 512>>>(bufA, W_hh1, (float*)0, hfin);
    // E: fc + sigmoid
    fc_sigmoid_kernel<<<1, HID>>>(hfin, W_fc, b_fc, out);
}

// round 7
// speedup vs baseline: 1.0990x; 1.0780x over previous
#include <cuda_runtime.h>
#include <math.h>

#define BATCH 256
#define SEQ   512
#define DIN   64
#define HID   256

__device__ float g_bufA[(size_t)BATCH * SEQ * HID];   // 128 MiB
__device__ float g_bufB[(size_t)BATCH * SEQ * HID];   // 128 MiB
__device__ float g_hfin[(size_t)BATCH * HID];

// ---------------------------------------------------------------------------
// helpers
// ---------------------------------------------------------------------------
__device__ __forceinline__ unsigned long long ffma2(unsigned long long a,
                                                    unsigned long long b,
                                                    unsigned long long c) {
    unsigned long long d;
    asm("fma.rn.f32x2 %0, %1, %2, %3;" : "=l"(d) : "l"(a), "l"(b), "l"(c));
    return d;
}
__device__ __forceinline__ float2 u2f(unsigned long long v) {
    float2 r;
    asm("mov.b64 {%0, %1}, %2;" : "=f"(r.x), "=f"(r.y) : "l"(v));
    return r;
}
__device__ __forceinline__ unsigned long long pack2(float a, float b) {
    unsigned long long r;
    asm("mov.b64 %0, {%1, %2};" : "=l"(r) : "f"(a), "f"(b));
    return r;
}
__device__ __forceinline__ float tanh_fast(float x) {
    float r;
    asm("tanh.approx.f32 %0, %1;" : "=f"(r) : "f"(x));
    return r;
}

// ---------------------------------------------------------------------------
// Recurrence — EXACT R4 champion (736 us/layer). 128 blocks x 512 threads,
// thread=(o, half), 2 batch rows per block, 96 weight floats in regs + 32 in
// smem, double-buffered h, tanh.approx epilogue. Do not perturb.
// ---------------------------------------------------------------------------
__global__ __launch_bounds__(512, 1) void rnn_recur_kernel(
    const float* __restrict__ xp,      // [BATCH, SEQ, HID] (bias pre-added)
    const float* __restrict__ Whh,     // [HID, HID]
    float* __restrict__ out_seq,       // [BATCH, SEQ, HID] or null
    float* __restrict__ out_final)     // [BATCH, HID] or null
{
    __shared__ __align__(16) float hbuf[2][2][272];
    __shared__ ulonglong2 wsm[8][512];  // 64 KB: weight pairs 48..63 / thread

    const int t     = threadIdx.x;
    const int o     = t >> 1;
    const int half  = t & 1;
    const int myrow = blockIdx.x * 2 + half;

    const float* wrow = Whh + o * HID + half * 128;
    unsigned long long w[48];
#pragma unroll
    for (int q = 0; q < 24; q++) {
        ulonglong2 v = reinterpret_cast<const ulonglong2*>(wrow)[q];
        w[2 * q]     = v.x;
        w[2 * q + 1] = v.y;
    }
#pragma unroll
    for (int j = 0; j < 8; j++)
        wsm[j][t] = reinterpret_cast<const ulonglong2*>(wrow)[24 + j];

    for (int idx = t; idx < 2 * 272; idx += 512)
        (&hbuf[0][0][0])[idx] = 0.0f;
    __syncthreads();

    const float* myxp  = xp + (size_t)myrow * SEQ * HID + o;
    float*       myout = out_seq ? out_seq + (size_t)myrow * SEQ * HID + o
                                 : (float*)0;

    int   buf   = 0;
    float hlast = 0.0f;

    for (int s = 0; s < SEQ; s++) {
        float xv = __ldg(myxp + (size_t)s * HID);

        const ulonglong2* h0 =
            reinterpret_cast<const ulonglong2*>(&hbuf[buf][0][half * 132]);
        const ulonglong2* h1 =
            reinterpret_cast<const ulonglong2*>(&hbuf[buf][1][half * 132]);

        unsigned long long a0 = 0ull, a1 = 0ull;
#pragma unroll
        for (int q = 0; q < 24; q++) {          // register-resident weights
            ulonglong2 v0 = h0[q], v1 = h1[q];
            a0 = ffma2(w[2 * q],     v0.x, a0);
            a0 = ffma2(w[2 * q + 1], v0.y, a0);
            a1 = ffma2(w[2 * q],     v1.x, a1);
            a1 = ffma2(w[2 * q + 1], v1.y, a1);
        }
#pragma unroll
        for (int j = 0; j < 8; j++) {           // smem-resident weights
            ulonglong2 wv = wsm[j][t];
            ulonglong2 v0 = h0[24 + j], v1 = h1[24 + j];
            a0 = ffma2(wv.x, v0.x, a0);
            a0 = ffma2(wv.y, v0.y, a0);
            a1 = ffma2(wv.x, v1.x, a1);
            a1 = ffma2(wv.y, v1.y, a1);
        }

        float2 f0 = u2f(a0), f1 = u2f(a1);
        float  d0 = f0.x + f0.y;
        float  d1 = f1.x + f1.y;
        d0 += __shfl_xor_sync(0xffffffffu, d0, 1);
        d1 += __shfl_xor_sync(0xffffffffu, d1, 1);

        float hn = tanh_fast((half ? d1 : d0) + xv);
        hlast = hn;

        hbuf[buf ^ 1][half][o + 4 * (o >> 7)] = hn;
        if (out_seq) myout[(size_t)s * HID] = hn;

        __syncthreads();
        buf ^= 1;
    }

    if (out_final) out_final[(size_t)myrow * HID + o] = hlast;
}

// ---------------------------------------------------------------------------
// GEMM v4: Y[M,256] = X[M,K] @ W[256,K]^T + (ba+bb)
// Block tile 128M x 128N, 256 threads, thread tile 8x8 (f32x2 accumulators).
// K-chunk 32 (vs 16 in v3): half the barriers, double the LDG prefetch
// distance. Double-buffered transposed smem staging.
// ---------------------------------------------------------------------------
template <int K>
__global__ __launch_bounds__(256, 2) void gemm4(
    const float* __restrict__ X, const float* __restrict__ W,
    const float* __restrict__ ba, const float* __restrict__ bb,
    float* __restrict__ Y)
{
    __shared__ float xs[2][32][128];   // 32 KB
    __shared__ float ws[2][32][128];   // 32 KB
    const int t  = threadIdx.x;
    const int tx = t & 15;    // N: 16 x 8
    const int ty = t >> 4;    // M: 16 x 8
    const size_t m0 = (size_t)blockIdx.x * 128;
    const int    n0 = blockIdx.y * 128;

    unsigned long long acc[8][4];
#pragma unroll
    for (int mi = 0; mi < 8; mi++)
#pragma unroll
        for (int ni = 0; ni < 4; ni++) acc[mi][ni] = 0ull;

    const int r = t & 127;
    const float* src_base = (t < 128) ? (X + (m0 + r) * K)
                                      : (W + (size_t)(n0 + r) * K);

    // prologue: load + stage chunk 0 (32 floats per thread)
    float4 pf[8];
#pragma unroll
    for (int q = 0; q < 8; q++)
        pf[q] = reinterpret_cast<const float4*>(src_base)[q];

    int sb = 0;
    {
        float* dst = (t < 128) ? &xs[0][0][r] : &ws[0][0][r];
#pragma unroll
        for (int q = 0; q < 8; q++) {
            dst[(4 * q + 0) * 128] = pf[q].x;
            dst[(4 * q + 1) * 128] = pf[q].y;
            dst[(4 * q + 2) * 128] = pf[q].z;
            dst[(4 * q + 3) * 128] = pf[q].w;
        }
    }
    __syncthreads();

    for (int kc = 0; kc < K; kc += 32) {
        const bool have_next = (kc + 32 < K);
        if (have_next) {
            const float4* src =
                reinterpret_cast<const float4*>(src_base + kc + 32);
#pragma unroll
            for (int q = 0; q < 8; q++) pf[q] = src[q];
        }

#pragma unroll
        for (int k = 0; k < 32; k++) {
            float4 a0 = *reinterpret_cast<const float4*>(&xs[sb][k][ty * 8]);
            float4 a1 = *reinterpret_cast<const float4*>(&xs[sb][k][ty * 8 + 4]);
            ulonglong2 b0 =
                *reinterpret_cast<const ulonglong2*>(&ws[sb][k][tx * 8]);
            ulonglong2 b1 =
                *reinterpret_cast<const ulonglong2*>(&ws[sb][k][tx * 8 + 4]);
            float am[8] = {a0.x, a0.y, a0.z, a0.w, a1.x, a1.y, a1.z, a1.w};
            unsigned long long bp0 = b0.x, bp1 = b0.y, bp2 = b1.x, bp3 = b1.y;
#pragma unroll
            for (int mi = 0; mi < 8; mi++) {
                unsigned long long am2 = pack2(am[mi], am[mi]);
                acc[mi][0] = ffma2(bp0, am2, acc[mi][0]);
                acc[mi][1] = ffma2(bp1, am2, acc[mi][1]);
                acc[mi][2] = ffma2(bp2, am2, acc[mi][2]);
                acc[mi][3] = ffma2(bp3, am2, acc[mi][3]);
            }
        }

        if (have_next) {
            float* dst = (t < 128) ? &xs[sb ^ 1][0][r] : &ws[sb ^ 1][0][r];
#pragma unroll
            for (int q = 0; q < 8; q++) {
                dst[(4 * q + 0) * 128] = pf[q].x;
                dst[(4 * q + 1) * 128] = pf[q].y;
                dst[(4 * q + 2) * 128] = pf[q].z;
                dst[(4 * q + 3) * 128] = pf[q].w;
            }
            __syncthreads();
            sb ^= 1;
        }
    }

    float bias[8];
#pragma unroll
    for (int i = 0; i < 8; i++)
        bias[i] = ba[n0 + tx * 8 + i] + bb[n0 + tx * 8 + i];

#pragma unroll
    for (int mi = 0; mi < 8; mi++) {
        float* yrow = Y + (m0 + ty * 8 + mi) * HID + n0 + tx * 8;
        float2 f0 = u2f(acc[mi][0]);
        float2 f1 = u2f(acc[mi][1]);
        float2 f2 = u2f(acc[mi][2]);
        float2 f3 = u2f(acc[mi][3]);
        float4 oA = make_float4(f0.x + bias[0], f0.y + bias[1],
                                f1.x + bias[2], f1.y + bias[3]);
        float4 oB = make_float4(f2.x + bias[4], f2.y + bias[5],
                                f3.x + bias[6], f3.y + bias[7]);
        reinterpret_cast<float4*>(yrow)[0] = oA;
        reinterpret_cast<float4*>(yrow)[1] = oB;
    }
}

// ---------------------------------------------------------------------------
// out[b] = sigmoid(h2[b,:] . Wfc + bfc)
// ---------------------------------------------------------------------------
__global__ void fc_sigmoid_kernel(const float* __restrict__ h2,
                                  const float* __restrict__ Wfc,
                                  const float* __restrict__ bfc,
                                  float* __restrict__ out)
{
    __shared__ float wf[HID];
    const int t = threadIdx.x;
    wf[t] = Wfc[t];
    __syncthreads();
    const float* hb = h2 + (size_t)t * HID;
    float s = 0.0f;
#pragma unroll 8
    for (int k = 0; k < HID; k++) s = fmaf(hb[k], wf[k], s);
    float z = s + bfc[0];
    out[t] = 1.0f / (1.0f + expf(-z));
}

// ---------------------------------------------------------------------------
// launch
// ---------------------------------------------------------------------------
extern "C" void kernel_launch(void* const* d_in, const int* in_sizes, int n_in,
                              void* d_out, int out_size)
{
    const float* x     = (const float*)d_in[0];
    const float* W_ih0 = (const float*)d_in[1];
    const float* W_hh0 = (const float*)d_in[2];
    const float* b_ih0 = (const float*)d_in[3];
    const float* b_hh0 = (const float*)d_in[4];
    const float* W_ih1 = (const float*)d_in[5];
    const float* W_hh1 = (const float*)d_in[6];
    const float* b_ih1 = (const float*)d_in[7];
    const float* b_hh1 = (const float*)d_in[8];
    const float* W_fc  = (const float*)d_in[9];
    const float* b_fc  = (const float*)d_in[10];
    float* out = (float*)d_out;

    float *bufA, *bufB, *hfin;
    cudaGetSymbolAddress((void**)&bufA, g_bufA);
    cudaGetSymbolAddress((void**)&bufB, g_bufB);
    cudaGetSymbolAddress((void**)&hfin, g_hfin);

    const dim3 ggrid((BATCH * SEQ) / 128, 2);

    // A: xp0 = x @ W_ih0^T + (b_ih0 + b_hh0)
    gemm4<DIN><<<ggrid, 256>>>(x, W_ih0, b_ih0, b_hh0, bufA);
    // B: layer-0 recurrence -> h1 sequence
    rnn_recur_kernel<<<BATCH / 2, 512>>>(bufA, W_hh0, bufB, (float*)0);
    // C: xp1 = h1 @ W_ih1^T + (b_ih1 + b_hh1)
    gemm4<HID><<<ggrid, 256>>>(bufB, W_ih1, b_ih1, b_hh1, bufA);
    // D: layer-1 recurrence -> final hidden only
    rnn_recur_kernel<<<BATCH / 2, 512>>>(bufA, W_hh1, (float*)0, hfin);
    // E: fc + sigmoid
    fc_sigmoid_kernel<<<1, HID>>>(hfin, W_fc, b_fc, out);
}

// round 10
// speedup vs baseline: 1.2244x; 1.1141x over previous
#include <cuda_runtime.h>
#include <cuda_bf16.h>
#include <math.h>
#include <stdint.h>

#define BATCH 256
#define SEQ   512
#define DIN   64
#define HID   256
#define MROWS (BATCH * SEQ)       // 131072

__device__ float g_bufA[(size_t)MROWS * HID];
__device__ float g_bufB[(size_t)MROWS * HID];
__device__ float g_hfin[(size_t)BATCH * HID];
__device__ __nv_bfloat16 g_xhi[(size_t)MROWS * DIN];
__device__ __nv_bfloat16 g_xlo[(size_t)MROWS * DIN];
__device__ __nv_bfloat16 g_hhi[(size_t)MROWS * HID];
__device__ __nv_bfloat16 g_hlo[(size_t)MROWS * HID];
__device__ __nv_bfloat16 g_whi[HID * HID];
__device__ __nv_bfloat16 g_wlo[HID * HID];

// ---------------------------------------------------------------------------
// helpers
// ---------------------------------------------------------------------------
__device__ __forceinline__ unsigned long long ffma2(unsigned long long a,
                                                    unsigned long long b,
                                                    unsigned long long c) {
    unsigned long long d;
    asm("fma.rn.f32x2 %0, %1, %2, %3;" : "=l"(d) : "l"(a), "l"(b), "l"(c));
    return d;
}
__device__ __forceinline__ float2 u2f(unsigned long long v) {
    float2 r;
    asm("mov.b64 {%0, %1}, %2;" : "=f"(r.x), "=f"(r.y) : "l"(v));
    return r;
}
__device__ __forceinline__ float tanh_fast(float x) {
    float r;
    asm("tanh.approx.f32 %0, %1;" : "=f"(r) : "f"(x));
    return r;
}
// mma.sync m16n8k16 bf16 -> f32 (base-arch instruction, works on sm_103)
__device__ __forceinline__ void mma16816(float* c, const uint32_t* a,
                                         uint32_t b0, uint32_t b1) {
    asm volatile(
        "mma.sync.aligned.m16n8k16.row.col.f32.bf16.bf16.f32 "
        "{%0,%1,%2,%3}, {%4,%5,%6,%7}, {%8,%9}, {%0,%1,%2,%3};"
        : "+f"(c[0]), "+f"(c[1]), "+f"(c[2]), "+f"(c[3])
        : "r"(a[0]), "r"(a[1]), "r"(a[2]), "r"(a[3]), "r"(b0), "r"(b1));
}

// ---------------------------------------------------------------------------
// f32 -> (bf16 hi, bf16 lo) split conversion, vectorized, grid-stride
// ---------------------------------------------------------------------------
__global__ void cvt_split_kernel(const float* __restrict__ in,
                                 __nv_bfloat16* __restrict__ hi,
                                 __nv_bfloat16* __restrict__ lo, int n4) {
    __nv_bfloat162* h2 = reinterpret_cast<__nv_bfloat162*>(hi);
    __nv_bfloat162* l2 = reinterpret_cast<__nv_bfloat162*>(lo);
    const float4* in4 = reinterpret_cast<const float4*>(in);
    for (int i = blockIdx.x * blockDim.x + threadIdx.x; i < n4;
         i += gridDim.x * blockDim.x) {
        float4 v = in4[i];
        __nv_bfloat16 a = __float2bfloat16(v.x), b = __float2bfloat16(v.y);
        __nv_bfloat16 c = __float2bfloat16(v.z), d = __float2bfloat16(v.w);
        __nv_bfloat16 ra = __float2bfloat16(v.x - __bfloat162float(a));
        __nv_bfloat16 rb = __float2bfloat16(v.y - __bfloat162float(b));
        __nv_bfloat16 rc = __float2bfloat16(v.z - __bfloat162float(c));
        __nv_bfloat16 rd = __float2bfloat16(v.w - __bfloat162float(d));
        h2[2 * i]     = __nv_bfloat162{a, b};
        h2[2 * i + 1] = __nv_bfloat162{c, d};
        l2[2 * i]     = __nv_bfloat162{ra, rb};
        l2[2 * i + 1] = __nv_bfloat162{rc, rd};
    }
}

// ---------------------------------------------------------------------------
// Tensor-core GEMM (mma.sync bf16x3): Y[M,256] = X[M,K] @ W[256,K]^T + bias
// 256 threads / 8 warps; CTA tile 128M x 128N; warp tile 32M x 64N.
// K staged in 64-wide bf16 chunks (hi+lo), smem row stride 72 elts
// (fragment LDS.32 reads bank-conflict-free). 3 accumulation passes:
// hi*hi + hi*lo + lo*hi.  grid = (M/128, 2).
// ---------------------------------------------------------------------------
#define GSTRIDE 72   // bf16 elements per smem row

template <int K>
__global__ __launch_bounds__(256) void gemm_mma(
    const __nv_bfloat16* __restrict__ Ahi, const __nv_bfloat16* __restrict__ Alo,
    const __nv_bfloat16* __restrict__ Bhi, const __nv_bfloat16* __restrict__ Blo,
    const float* __restrict__ ba, const float* __restrict__ bb,
    float* __restrict__ Y)
{
    extern __shared__ char smraw[];
    __nv_bfloat16* Ahs = reinterpret_cast<__nv_bfloat16*>(smraw);
    __nv_bfloat16* Als = Ahs + 128 * GSTRIDE;
    __nv_bfloat16* Bhs = Als + 128 * GSTRIDE;
    __nv_bfloat16* Bls = Bhs + 128 * GSTRIDE;
    float* bias = reinterpret_cast<float*>(Bls + 128 * GSTRIDE);

    const int t      = threadIdx.x;
    const int lane   = t & 31;
    const int wid    = t >> 5;
    const int warp_m = wid >> 1;           // 0..3 -> 32 M-rows
    const int warp_n = wid & 1;            // 0..1 -> 64 N-cols
    const size_t m0  = (size_t)blockIdx.x * 128;
    const int    n0  = blockIdx.y * 128;

    if (t < 128) bias[t] = ba[n0 + t] + bb[n0 + t];

    float acc[2][8][4];
#pragma unroll
    for (int mt = 0; mt < 2; mt++)
#pragma unroll
        for (int nt = 0; nt < 8; nt++)
#pragma unroll
            for (int i = 0; i < 4; i++) acc[mt][nt][i] = 0.0f;

    const int srow = t >> 1;       // staging row 0..127
    const int shalf = t & 1;       // which 32-elt half of the 64-k chunk

    for (int kc = 0; kc < K; kc += 64) {
        // ---- stage A & B chunks (hi+lo), 32 bf16 per thread per tile ----
        {
            const uint4* sAh = reinterpret_cast<const uint4*>(
                Ahi + (m0 + srow) * K + kc + shalf * 32);
            const uint4* sAl = reinterpret_cast<const uint4*>(
                Alo + (m0 + srow) * K + kc + shalf * 32);
            const uint4* sBh = reinterpret_cast<const uint4*>(
                Bhi + (size_t)(n0 + srow) * K + kc + shalf * 32);
            const uint4* sBl = reinterpret_cast<const uint4*>(
                Blo + (size_t)(n0 + srow) * K + kc + shalf * 32);
            uint4* dAh = reinterpret_cast<uint4*>(Ahs + srow * GSTRIDE + shalf * 32);
            uint4* dAl = reinterpret_cast<uint4*>(Als + srow * GSTRIDE + shalf * 32);
            uint4* dBh = reinterpret_cast<uint4*>(Bhs + srow * GSTRIDE + shalf * 32);
            uint4* dBl = reinterpret_cast<uint4*>(Bls + srow * GSTRIDE + shalf * 32);
#pragma unroll
            for (int q = 0; q < 4; q++) {
                dAh[q] = sAh[q];
                dAl[q] = sAl[q];
                dBh[q] = sBh[q];
                dBl[q] = sBl[q];
            }
        }
        __syncthreads();

#pragma unroll
        for (int ks = 0; ks < 4; ks++) {
            const int k0 = ks * 16;
            // ---- A fragments (2 m-tiles, hi+lo) ----
            uint32_t ah[2][4], al[2][4];
#pragma unroll
            for (int mt = 0; mt < 2; mt++) {
                int idx = (warp_m * 32 + mt * 16 + (lane >> 2)) * GSTRIDE +
                          k0 + (lane & 3) * 2;
                ah[mt][0] = *reinterpret_cast<const uint32_t*>(&Ahs[idx]);
                ah[mt][1] = *reinterpret_cast<const uint32_t*>(&Ahs[idx + 8 * GSTRIDE]);
                ah[mt][2] = *reinterpret_cast<const uint32_t*>(&Ahs[idx + 8]);
                ah[mt][3] = *reinterpret_cast<const uint32_t*>(&Ahs[idx + 8 * GSTRIDE + 8]);
                al[mt][0] = *reinterpret_cast<const uint32_t*>(&Als[idx]);
                al[mt][1] = *reinterpret_cast<const uint32_t*>(&Als[idx + 8 * GSTRIDE]);
                al[mt][2] = *reinterpret_cast<const uint32_t*>(&Als[idx + 8]);
                al[mt][3] = *reinterpret_cast<const uint32_t*>(&Als[idx + 8 * GSTRIDE + 8]);
            }
#pragma unroll
            for (int nt = 0; nt < 8; nt++) {
                int idxb = (warp_n * 64 + nt * 8 + (lane >> 2)) * GSTRIDE +
                           k0 + (lane & 3) * 2;
                uint32_t bh0 = *reinterpret_cast<const uint32_t*>(&Bhs[idxb]);
                uint32_t bh1 = *reinterpret_cast<const uint32_t*>(&Bhs[idxb + 8]);
                uint32_t bl0 = *reinterpret_cast<const uint32_t*>(&Bls[idxb]);
                uint32_t bl1 = *reinterpret_cast<const uint32_t*>(&Bls[idxb + 8]);
#pragma unroll
                for (int mt = 0; mt < 2; mt++) {
                    mma16816(acc[mt][nt], ah[mt], bh0, bh1);   // hi*hi
                    mma16816(acc[mt][nt], ah[mt], bl0, bl1);   // hi*lo
                    mma16816(acc[mt][nt], al[mt], bh0, bh1);   // lo*hi
                }
            }
        }
        __syncthreads();
    }

    // ---- epilogue: bias add + store ----
#pragma unroll
    for (int mt = 0; mt < 2; mt++) {
        const size_t rbase = m0 + warp_m * 32 + mt * 16 + (lane >> 2);
#pragma unroll
        for (int nt = 0; nt < 8; nt++) {
            const int cl = warp_n * 64 + nt * 8 + (lane & 3) * 2;
            float b0 = bias[cl], b1 = bias[cl + 1];
            float2 v0 = make_float2(acc[mt][nt][0] + b0, acc[mt][nt][1] + b1);
            float2 v1 = make_float2(acc[mt][nt][2] + b0, acc[mt][nt][3] + b1);
            *reinterpret_cast<float2*>(Y + rbase * HID + n0 + cl) = v0;
            *reinterpret_cast<float2*>(Y + (rbase + 8) * HID + n0 + cl) = v1;
        }
    }
}

#define GEMM_SMEM (4 * 128 * GSTRIDE * 2 + 128 * 4)   // 74240 bytes

// ---------------------------------------------------------------------------
// Recurrence — EXACT champion (736 us/layer). Do not perturb.
// ---------------------------------------------------------------------------
__global__ __launch_bounds__(512, 1) void rnn_recur_kernel(
    const float* __restrict__ xp, const float* __restrict__ Whh,
    float* __restrict__ out_seq, float* __restrict__ out_final)
{
    __shared__ __align__(16) float hbuf[2][2][272];
    __shared__ ulonglong2 wsm[8][512];

    const int t     = threadIdx.x;
    const int o     = t >> 1;
    const int half  = t & 1;
    const int myrow = blockIdx.x * 2 + half;

    const float* wrow = Whh + o * HID + half * 128;
    unsigned long long w[48];
#pragma unroll
    for (int q = 0; q < 24; q++) {
        ulonglong2 v = reinterpret_cast<const ulonglong2*>(wrow)[q];
        w[2 * q]     = v.x;
        w[2 * q + 1] = v.y;
    }
#pragma unroll
    for (int j = 0; j < 8; j++)
        wsm[j][t] = reinterpret_cast<const ulonglong2*>(wrow)[24 + j];

    for (int idx = t; idx < 2 * 272; idx += 512)
        (&hbuf[0][0][0])[idx] = 0.0f;
    __syncthreads();

    const float* myxp  = xp + (size_t)myrow * SEQ * HID + o;
    float*       myout = out_seq ? out_seq + (size_t)myrow * SEQ * HID + o
                                 : (float*)0;

    int   buf   = 0;
    float hlast = 0.0f;

    for (int s = 0; s < SEQ; s++) {
        float xv = __ldg(myxp + (size_t)s * HID);

        const ulonglong2* h0 =
            reinterpret_cast<const ulonglong2*>(&hbuf[buf][0][half * 132]);
        const ulonglong2* h1 =
            reinterpret_cast<const ulonglong2*>(&hbuf[buf][1][half * 132]);

        unsigned long long a0 = 0ull, a1 = 0ull;
#pragma unroll
        for (int q = 0; q < 24; q++) {
            ulonglong2 v0 = h0[q], v1 = h1[q];
            a0 = ffma2(w[2 * q],     v0.x, a0);
            a0 = ffma2(w[2 * q + 1], v0.y, a0);
            a1 = ffma2(w[2 * q],     v1.x, a1);
            a1 = ffma2(w[2 * q + 1], v1.y, a1);
        }
#pragma unroll
        for (int j = 0; j < 8; j++) {
            ulonglong2 wv = wsm[j][t];
            ulonglong2 v0 = h0[24 + j], v1 = h1[24 + j];
            a0 = ffma2(wv.x, v0.x, a0);
            a0 = ffma2(wv.y, v0.y, a0);
            a1 = ffma2(wv.x, v1.x, a1);
            a1 = ffma2(wv.y, v1.y, a1);
        }

        float2 f0 = u2f(a0), f1 = u2f(a1);
        float  d0 = f0.x + f0.y;
        float  d1 = f1.x + f1.y;
        d0 += __shfl_xor_sync(0xffffffffu, d0, 1);
        d1 += __shfl_xor_sync(0xffffffffu, d1, 1);

        float hn = tanh_fast((half ? d1 : d0) + xv);
        hlast = hn;

        hbuf[buf ^ 1][half][o + 4 * (o >> 7)] = hn;
        if (out_seq) myout[(size_t)s * HID] = hn;

        __syncthreads();
        buf ^= 1;
    }

    if (out_final) out_final[(size_t)myrow * HID + o] = hlast;
}

// ---------------------------------------------------------------------------
// out[b] = sigmoid(h2[b,:] . Wfc + bfc)
// ---------------------------------------------------------------------------
__global__ void fc_sigmoid_kernel(const float* __restrict__ h2,
                                  const float* __restrict__ Wfc,
                                  const float* __restrict__ bfc,
                                  float* __restrict__ out)
{
    __shared__ float wf[HID];
    const int t = threadIdx.x;
    wf[t] = Wfc[t];
    __syncthreads();
    const float* hb = h2 + (size_t)t * HID;
    float s = 0.0f;
#pragma unroll 8
    for (int k = 0; k < HID; k++) s = fmaf(hb[k], wf[k], s);
    float z = s + bfc[0];
    out[t] = 1.0f / (1.0f + expf(-z));
}

// ---------------------------------------------------------------------------
// launch
// ---------------------------------------------------------------------------
extern "C" void kernel_launch(void* const* d_in, const int* in_sizes, int n_in,
                              void* d_out, int out_size)
{
    const float* x     = (const float*)d_in[0];
    const float* W_ih0 = (const float*)d_in[1];
    const float* W_hh0 = (const float*)d_in[2];
    const float* b_ih0 = (const float*)d_in[3];
    const float* b_hh0 = (const float*)d_in[4];
    const float* W_ih1 = (const float*)d_in[5];
    const float* W_hh1 = (const float*)d_in[6];
    const float* b_ih1 = (const float*)d_in[7];
    const float* b_hh1 = (const float*)d_in[8];
    const float* W_fc  = (const float*)d_in[9];
    const float* b_fc  = (const float*)d_in[10];
    float* out = (float*)d_out;

    float *bufA, *bufB, *hfin;
    __nv_bfloat16 *xhi, *xlo, *hhi, *hlo, *whi, *wlo;
    cudaGetSymbolAddress((void**)&bufA, g_bufA);
    cudaGetSymbolAddress((void**)&bufB, g_bufB);
    cudaGetSymbolAddress((void**)&hfin, g_hfin);
    cudaGetSymbolAddress((void**)&xhi, g_xhi);
    cudaGetSymbolAddress((void**)&xlo, g_xlo);
    cudaGetSymbolAddress((void**)&hhi, g_hhi);
    cudaGetSymbolAddress((void**)&hlo, g_hlo);
    cudaGetSymbolAddress((void**)&whi, g_whi);
    cudaGetSymbolAddress((void**)&wlo, g_wlo);

    cudaFuncSetAttribute(gemm_mma<DIN>,
                         cudaFuncAttributeMaxDynamicSharedMemorySize, GEMM_SMEM);
    cudaFuncSetAttribute(gemm_mma<HID>,
                         cudaFuncAttributeMaxDynamicSharedMemorySize, GEMM_SMEM);

    const dim3 ggrid(MROWS / 128, 2);

    // ---- phase A: xp0 = x @ W_ih0^T + (b_ih0+b_hh0), tensor cores ----
    cvt_split_kernel<<<1024, 256>>>(x, xhi, xlo, MROWS * DIN / 4);
    cvt_split_kernel<<<64, 256>>>(W_ih0, whi, wlo, HID * DIN / 4);
    gemm_mma<DIN><<<ggrid, 256, GEMM_SMEM>>>(xhi, xlo, whi, wlo,
                                             b_ih0, b_hh0, bufA);
    // ---- phase B: layer-0 recurrence ----
    rnn_recur_kernel<<<BATCH / 2, 512>>>(bufA, W_hh0, bufB, (float*)0);
    // ---- phase C: xp1 = h1 @ W_ih1^T + (b_ih1+b_hh1) ----
    cvt_split_kernel<<<2048, 256>>>(bufB, hhi, hlo, MROWS * HID / 4);
    cvt_split_kernel<<<64, 256>>>(W_ih1, whi, wlo, HID * HID / 4);
    gemm_mma<HID><<<ggrid, 256, GEMM_SMEM>>>(hhi, hlo, whi, wlo,
                                             b_ih1, b_hh1, bufA);
    // ---- phase D: layer-1 recurrence ----
    rnn_recur_kernel<<<BATCH / 2, 512>>>(bufA, W_hh1, (float*)0, hfin);
    // ---- phase E: fc + sigmoid ----
    fc_sigmoid_kernel<<<1, HID>>>(hfin, W_fc, b_fc, out);
}